// round 4
// baseline (speedup 1.0000x reference)
#include <cuda_runtime.h>
#include <cuda_fp16.h>
#include <cstdint>

// ---------------- problem constants ----------------
#define DIMC   512
#define NHEADS 16
#define SSZ    4
#define BWIN   2048          // 32 batches * 64 windows
#define MROWS  131072        // BWIN * 64 == B*L
#define CHID   2048          // mlp hidden

// ---------------- scratch (device globals; no allocs allowed) ----------------
__device__ __half g_XN1[(size_t)MROWS * DIMC];
__device__ __half g_QKV[(size_t)MROWS * 3 * DIMC];
__device__ __half g_O  [(size_t)MROWS * DIMC];
__device__ __half g_XN2[(size_t)MROWS * DIMC];
__device__ __half g_H1 [(size_t)MROWS * CHID];
__device__ __half g_Wq [3 * DIMC * DIMC];
__device__ __half g_Wp [DIMC * DIMC];
__device__ __half g_W1 [CHID * DIMC];
__device__ __half g_W2 [DIMC * CHID];

// ---------------- helpers ----------------
__device__ __forceinline__ float gelu_f(float x) {
    return 0.5f * x * (1.0f + erff(x * 0.7071067811865475f));
}

__device__ __forceinline__ uint32_t smem_u32(const void* p) {
    return (uint32_t)__cvta_generic_to_shared(p);
}

// token index in window order -> token index in (B,H,W) order (shift mapping)
__device__ __forceinline__ size_t win_to_img(int t) {
    int b_   = t >> 6, nn = t & 63;
    int bimg = b_ >> 6, widx = b_ & 63;
    int gh = ((widx >> 3) << 3) + (nn >> 3);
    int gw = ((widx & 7) << 3) + (nn & 7);
    int sh = (gh + SSZ) & 63;
    int sw = (gw + SSZ) & 63;
    return ((size_t)bimg << 12) + (size_t)(sh << 6) + (size_t)sw;
}

#define LDSM_X4(r0, r1, r2, r3, addr)                                          \
    asm volatile("ldmatrix.sync.aligned.m8n8.x4.shared.b16 {%0,%1,%2,%3}, [%4];" \
                 : "=r"(r0), "=r"(r1), "=r"(r2), "=r"(r3) : "r"(addr))

#define MMA16816(d, a, b0, b1)                                                 \
    asm volatile(                                                              \
        "mma.sync.aligned.m16n8k16.row.col.f32.f16.f16.f32 "                   \
        "{%0,%1,%2,%3},{%4,%5,%6,%7},{%8,%9},{%0,%1,%2,%3};"                   \
        : "+f"((d)[0]), "+f"((d)[1]), "+f"((d)[2]), "+f"((d)[3])               \
        : "r"((a)[0]), "r"((a)[1]), "r"((a)[2]), "r"((a)[3]),                  \
          "r"(b0), "r"(b1))

// ---------------- weight convert (fp32 -> fp16) ----------------
template <int WHICH>
__global__ void cvt_k(const float* __restrict__ in, int n) {
    __half* o = WHICH == 0 ? g_Wq : WHICH == 1 ? g_Wp : WHICH == 2 ? g_W1 : g_W2;
    int i = blockIdx.x * 256 + threadIdx.x;
    if (i < n) o[i] = __float2half(in[i]);
}

// ---------------- layernorm (warp per token), optional shift+window remap ----
template <bool SHIFT>
__global__ void __launch_bounds__(256) ln_kernel(const float* __restrict__ xin,
                                                 const float* __restrict__ gamma,
                                                 const float* __restrict__ beta) {
    int t    = (blockIdx.x * 256 + threadIdx.x) >> 5;
    int lane = threadIdx.x & 31;
    __half* ob = SHIFT ? g_XN1 : g_XN2;

    size_t src = SHIFT ? win_to_img(t) : (size_t)t;
    const float* row = xin + src * DIMC;

    float4 v[4];
    float sum = 0.f, sq = 0.f;
#pragma unroll
    for (int p = 0; p < 4; p++) {
        v[p] = *(const float4*)(row + p * 128 + lane * 4);
        sum += v[p].x + v[p].y + v[p].z + v[p].w;
        sq  += v[p].x * v[p].x + v[p].y * v[p].y + v[p].z * v[p].z + v[p].w * v[p].w;
    }
#pragma unroll
    for (int o = 16; o > 0; o >>= 1) {
        sum += __shfl_xor_sync(0xffffffffu, sum, o);
        sq  += __shfl_xor_sync(0xffffffffu, sq, o);
    }
    float mu   = sum * (1.f / 512.f);
    float var  = sq * (1.f / 512.f) - mu * mu;
    float rstd = rsqrtf(var + 1e-5f);

    __half* orow = ob + (size_t)t * DIMC;
#pragma unroll
    for (int p = 0; p < 4; p++) {
        int c = p * 128 + lane * 4;
        float4 g4 = *(const float4*)(gamma + c);
        float4 b4 = *(const float4*)(beta + c);
        __half2 h0 = __floats2half2_rn((v[p].x - mu) * rstd * g4.x + b4.x,
                                       (v[p].y - mu) * rstd * g4.y + b4.y);
        __half2 h1 = __floats2half2_rn((v[p].z - mu) * rstd * g4.z + b4.z,
                                       (v[p].w - mu) * rstd * g4.w + b4.w);
        uint2 u;
        u.x = *(uint32_t*)&h0;
        u.y = *(uint32_t*)&h1;
        *(uint2*)(orow + c) = u;
    }
}

// ---------------- fp16 mma.sync GEMM: C[M,N] = A[M,K] @ W[N,K]^T ------------
// BM=128, BN=256, BK=32, 4-stage cp.async pipeline, XOR-swizzled smem,
// 8 warps each computing a 64x64 sub-tile (4 MMA per ldmatrix issue).
// OP 0: -> g_QKV(f16) = acc + bias
// OP 1: -> out[remap] = aux[remap] + acc + bias   (fp32)
// OP 2: -> g_H1(f16) = gelu(acc + bias)
// OP 3: -> out += acc + bias                       (fp32)
template <int NTOT, int KTOT, int OP>
__global__ void __launch_bounds__(256, 1) gemm_f16(const float* __restrict__ bias,
                                                   const float* __restrict__ aux,
                                                   float* __restrict__ outp) {
    constexpr int BM = 128, BN = 256, BK = 32, STAGES = 4;
    constexpr int KT = KTOT / BK;
    constexpr uint32_t AB    = BM * BK * 2;   // 8KB
    constexpr uint32_t BB    = BN * BK * 2;   // 16KB
    constexpr uint32_t STAGE = AB + BB;       // 24KB

    extern __shared__ char smem[];
    const uint32_t sbase = smem_u32(smem);
    const int tid = threadIdx.x;

    const __half* A;
    const __half* Bw;
    if (OP == 0)      { A = g_XN1; Bw = g_Wq; }
    else if (OP == 1) { A = g_O;   Bw = g_Wp; }
    else if (OP == 2) { A = g_XN2; Bw = g_W1; }
    else              { A = g_H1;  Bw = g_W2; }

    const int m0 = blockIdx.y * BM;
    const int n0 = blockIdx.x * BN;

    auto load_tile = [&](int kt, int s) {
        const __half* gA = A + (size_t)m0 * KTOT + kt * BK;
        {
            int idx = tid;                    // 512 chunks / 256 threads = 2
#pragma unroll
            for (int i = 0; i < 2; i++) {
                int r = idx >> 2, g = idx & 3;
                uint32_t dst = sbase + (uint32_t)s * STAGE +
                               (uint32_t)(r * 64 + ((g ^ ((r >> 1) & 3)) << 4));
                const __half* src = gA + (size_t)r * KTOT + g * 8;
                asm volatile("cp.async.cg.shared.global [%0], [%1], 16;\n" ::"r"(dst), "l"(src));
                idx += 256;
            }
        }
        const __half* gB = Bw + (size_t)n0 * KTOT + kt * BK;
        {
            int idx = tid;                    // 1024 chunks / 256 threads = 4
#pragma unroll
            for (int i = 0; i < 4; i++) {
                int r = idx >> 2, g = idx & 3;
                uint32_t dst = sbase + (uint32_t)s * STAGE + AB +
                               (uint32_t)(r * 64 + ((g ^ ((r >> 1) & 3)) << 4));
                const __half* src = gB + (size_t)r * KTOT + g * 8;
                asm volatile("cp.async.cg.shared.global [%0], [%1], 16;\n" ::"r"(dst), "l"(src));
                idx += 256;
            }
        }
        asm volatile("cp.async.commit_group;\n");
    };

    const int w    = tid >> 5;
    const int wm   = w >> 2;    // 0..1 (64 rows)
    const int wn   = w & 3;     // 0..3 (64 cols)
    const int lane = tid & 31;
    const int grp  = lane >> 2;
    const int tig  = lane & 3;

    float acc[4][8][4];
#pragma unroll
    for (int i = 0; i < 4; i++)
#pragma unroll
        for (int j = 0; j < 8; j++)
#pragma unroll
            for (int r = 0; r < 4; r++) acc[i][j][r] = 0.f;

    // ldmatrix lane addressing
    const int a_row  = wm * 64 + (lane & 15);                 // + mt*16
    const int a_chk0 = lane >> 4;                              // + ks*2
    const int b_row  = wn * 64 + (lane & 7) + ((lane >> 4) << 3);  // + nt2*16
    const int b_chk0 = (lane >> 3) & 1;                        // + ks*2

    load_tile(0, 0);
    load_tile(1, 1);
    load_tile(2, 2);

#pragma unroll 1
    for (int kt = 0; kt < KT; ++kt) {
        if (kt + 3 < KT) asm volatile("cp.async.wait_group 2;\n");
        else             asm volatile("cp.async.wait_group 0;\n");
        __syncthreads();

        if (kt + 3 < KT) load_tile(kt + 3, (kt + 3) % STAGES);

        const uint32_t stA = sbase + (uint32_t)(kt % STAGES) * STAGE;
        const uint32_t stB = stA + AB;

#pragma unroll
        for (int ks = 0; ks < 2; ++ks) {
            uint32_t a[4][4], b[4][4];
#pragma unroll
            for (int mt = 0; mt < 4; ++mt) {
                int r = a_row + mt * 16;
                int c = ks * 2 + a_chk0;
                uint32_t ad = stA + (uint32_t)(r * 64 + ((c ^ ((r >> 1) & 3)) << 4));
                LDSM_X4(a[mt][0], a[mt][1], a[mt][2], a[mt][3], ad);
            }
#pragma unroll
            for (int nt2 = 0; nt2 < 4; ++nt2) {
                int r = b_row + nt2 * 16;
                int c = ks * 2 + b_chk0;
                uint32_t bd = stB + (uint32_t)(r * 64 + ((c ^ ((r >> 1) & 3)) << 4));
                LDSM_X4(b[nt2][0], b[nt2][1], b[nt2][2], b[nt2][3], bd);
            }
#pragma unroll
            for (int mt = 0; mt < 4; ++mt)
#pragma unroll
                for (int nt = 0; nt < 8; ++nt)
                    MMA16816(acc[mt][nt], a[mt], b[nt >> 1][(nt & 1) * 2], b[nt >> 1][(nt & 1) * 2 + 1]);
        }
    }

    // ---- epilogue ----
#pragma unroll
    for (int mt = 0; mt < 4; ++mt) {
        int r_lo = m0 + wm * 64 + mt * 16 + grp;
        int r_hi = r_lo + 8;
        size_t d_lo = 0, d_hi = 0;
        if (OP == 1) {
            d_lo = win_to_img(r_lo) * DIMC;
            d_hi = win_to_img(r_hi) * DIMC;
        }
#pragma unroll
        for (int nt = 0; nt < 8; ++nt) {
            int c0 = n0 + wn * 64 + nt * 8 + 2 * tig;
            float b0 = bias[c0], b1 = bias[c0 + 1];
            float v00 = acc[mt][nt][0] + b0;
            float v01 = acc[mt][nt][1] + b1;
            float v10 = acc[mt][nt][2] + b0;
            float v11 = acc[mt][nt][3] + b1;
            if (OP == 0) {
                *(__half2*)(g_QKV + (size_t)r_lo * NTOT + c0) = __floats2half2_rn(v00, v01);
                *(__half2*)(g_QKV + (size_t)r_hi * NTOT + c0) = __floats2half2_rn(v10, v11);
            } else if (OP == 1) {
                float2 a0 = *(const float2*)(aux + d_lo + c0);
                float2 a1 = *(const float2*)(aux + d_hi + c0);
                *(float2*)(outp + d_lo + c0) = make_float2(a0.x + v00, a0.y + v01);
                *(float2*)(outp + d_hi + c0) = make_float2(a1.x + v10, a1.y + v11);
            } else if (OP == 2) {
                *(__half2*)(g_H1 + (size_t)r_lo * NTOT + c0) =
                    __floats2half2_rn(gelu_f(v00), gelu_f(v01));
                *(__half2*)(g_H1 + (size_t)r_hi * NTOT + c0) =
                    __floats2half2_rn(gelu_f(v10), gelu_f(v11));
            } else {
                size_t o0 = (size_t)r_lo * NTOT + c0;
                size_t o1 = (size_t)r_hi * NTOT + c0;
                float2 p0 = *(const float2*)(outp + o0);
                float2 p1 = *(const float2*)(outp + o1);
                *(float2*)(outp + o0) = make_float2(p0.x + v00, p0.y + v01);
                *(float2*)(outp + o1) = make_float2(p1.x + v10, p1.y + v11);
            }
        }
    }
}

// ---------------- attention: one block per (window, head) -------------------
__global__ void __launch_bounds__(64) attn_kernel(const float* __restrict__ rpb) {
    __shared__ float sk[64][36];
    __shared__ float sv[64][36];
    __shared__ float srpb[225];
    __shared__ int   slab[64];

    int bh = blockIdx.x;
    int b_ = bh >> 4;
    int h  = bh & 15;
    int n  = threadIdx.x;

    const __half* qkvrow = g_QKV + (size_t)(b_ * 64 + n) * (3 * DIMC) + h * 32;

    float q[32];
#pragma unroll
    for (int j = 0; j < 4; j++) {
        uint4 u = *(const uint4*)(qkvrow + j * 8);
        const __half2* hp = (const __half2*)&u;
#pragma unroll
        for (int e = 0; e < 4; e++) {
            float2 f = __half22float2(hp[e]);
            q[j * 8 + e * 2]     = f.x;
            q[j * 8 + e * 2 + 1] = f.y;
        }
    }
#pragma unroll
    for (int j = 0; j < 4; j++) {
        uint4 u = *(const uint4*)(qkvrow + DIMC + j * 8);
        const __half2* hp = (const __half2*)&u;
#pragma unroll
        for (int e = 0; e < 4; e++) {
            float2 f = __half22float2(hp[e]);
            sk[n][j * 8 + e * 2]     = f.x;
            sk[n][j * 8 + e * 2 + 1] = f.y;
        }
    }
#pragma unroll
    for (int j = 0; j < 4; j++) {
        uint4 u = *(const uint4*)(qkvrow + 2 * DIMC + j * 8);
        const __half2* hp = (const __half2*)&u;
#pragma unroll
        for (int e = 0; e < 4; e++) {
            float2 f = __half22float2(hp[e]);
            sv[n][j * 8 + e * 2]     = f.x;
            sv[n][j * 8 + e * 2 + 1] = f.y;
        }
    }

    for (int i = n; i < 225; i += 64) srpb[i] = rpb[i * NHEADS + h];

    {
        int widx = b_ & 63;
        int gh = ((widx >> 3) << 3) + (n >> 3);
        int gw = ((widx & 7) << 3) + (n & 7);
        int zh = gh < 56 ? 0 : (gh < 60 ? 1 : 2);
        int zw = gw < 56 ? 0 : (gw < 60 ? 1 : 2);
        slab[n] = zh * 3 + zw;
    }
    __syncthreads();

    const float scale = 0.17677669529663687f;  // 1/sqrt(32)
    int   mylab = slab[n];
    int   rh = n >> 3, rw = n & 7;

    float s[64];
#pragma unroll
    for (int m = 0; m < 64; m++) {
        float a0 = 0.f, a1 = 0.f, a2 = 0.f, a3 = 0.f;
#pragma unroll
        for (int j = 0; j < 8; j++) {
            float4 kk = *(const float4*)&sk[m][j * 4];
            a0 += q[j * 4]     * kk.x;
            a1 += q[j * 4 + 1] * kk.y;
            a2 += q[j * 4 + 2] * kk.z;
            a3 += q[j * 4 + 3] * kk.w;
        }
        int idx = (rh - (m >> 3) + 7) * 15 + (rw - (m & 7) + 7);
        float msk = (mylab == slab[m]) ? 0.f : -100.f;
        s[m] = ((a0 + a1) + (a2 + a3)) * scale + srpb[idx] + msk;
    }

    float mx = -1e30f;
#pragma unroll
    for (int m = 0; m < 64; m++) mx = fmaxf(mx, s[m]);
    float sum = 0.f;
#pragma unroll
    for (int m = 0; m < 64; m++) {
        s[m] = __expf(s[m] - mx);
        sum += s[m];
    }
    float inv = 1.f / sum;

    float o[32];
#pragma unroll
    for (int d = 0; d < 32; d++) o[d] = 0.f;
#pragma unroll
    for (int m = 0; m < 64; m++) {
        float p = s[m] * inv;
#pragma unroll
        for (int j = 0; j < 8; j++) {
            float4 vv = *(const float4*)&sv[m][j * 4];
            o[j * 4]     += p * vv.x;
            o[j * 4 + 1] += p * vv.y;
            o[j * 4 + 2] += p * vv.z;
            o[j * 4 + 3] += p * vv.w;
        }
    }

    __half* orow = g_O + (size_t)(b_ * 64 + n) * DIMC + h * 32;
#pragma unroll
    for (int j = 0; j < 4; j++) {
        __half2 h0 = __floats2half2_rn(o[j * 8],     o[j * 8 + 1]);
        __half2 h1 = __floats2half2_rn(o[j * 8 + 2], o[j * 8 + 3]);
        __half2 h2 = __floats2half2_rn(o[j * 8 + 4], o[j * 8 + 5]);
        __half2 h3 = __floats2half2_rn(o[j * 8 + 6], o[j * 8 + 7]);
        uint4 u;
        u.x = *(uint32_t*)&h0;
        u.y = *(uint32_t*)&h1;
        u.z = *(uint32_t*)&h2;
        u.w = *(uint32_t*)&h3;
        *(uint4*)(orow + j * 8) = u;
    }
}

// ---------------- host launcher ----------------
extern "C" void kernel_launch(void* const* d_in, const int* in_sizes, int n_in,
                              void* d_out, int out_size) {
    const float* x      = (const float*)d_in[0];
    const float* n1g    = (const float*)d_in[1];
    const float* n1b    = (const float*)d_in[2];
    const float* qkv_w  = (const float*)d_in[3];
    const float* qkv_b  = (const float*)d_in[4];
    const float* proj_w = (const float*)d_in[5];
    const float* proj_b = (const float*)d_in[6];
    const float* rpb    = (const float*)d_in[7];
    const float* n2g    = (const float*)d_in[8];
    const float* n2b    = (const float*)d_in[9];
    const float* fc1_w  = (const float*)d_in[10];
    const float* fc1_b  = (const float*)d_in[11];
    const float* fc2_w  = (const float*)d_in[12];
    const float* fc2_b  = (const float*)d_in[13];
    float* out = (float*)d_out;

    constexpr int SMEMB = 4 * (128 * 32 * 2 + 256 * 32 * 2);  // 98304 bytes

    cudaFuncSetAttribute(gemm_f16<1536, 512, 0>, cudaFuncAttributeMaxDynamicSharedMemorySize, SMEMB);
    cudaFuncSetAttribute(gemm_f16<512,  512, 1>, cudaFuncAttributeMaxDynamicSharedMemorySize, SMEMB);
    cudaFuncSetAttribute(gemm_f16<2048, 512, 2>, cudaFuncAttributeMaxDynamicSharedMemorySize, SMEMB);
    cudaFuncSetAttribute(gemm_f16<512, 2048, 3>, cudaFuncAttributeMaxDynamicSharedMemorySize, SMEMB);

    // weights -> fp16 copies
    cvt_k<0><<<(3 * DIMC * DIMC + 255) / 256, 256>>>(qkv_w, 3 * DIMC * DIMC);
    cvt_k<1><<<(DIMC * DIMC + 255) / 256, 256>>>(proj_w, DIMC * DIMC);
    cvt_k<2><<<(CHID * DIMC + 255) / 256, 256>>>(fc1_w, CHID * DIMC);
    cvt_k<3><<<(DIMC * CHID + 255) / 256, 256>>>(fc2_w, DIMC * CHID);

    // LN1 + shift + window partition
    ln_kernel<true><<<MROWS / 8, 256>>>(x, n1g, n1b);

    // QKV projection
    gemm_f16<1536, 512, 0><<<dim3(1536 / 256, MROWS / 128), 256, SMEMB>>>(qkv_b, nullptr, nullptr);

    // windowed attention
    attn_kernel<<<BWIN * NHEADS, 64>>>(rpb);

    // output projection + window reverse + shift + residual -> d_out
    gemm_f16<512, 512, 1><<<dim3(512 / 256, MROWS / 128), 256, SMEMB>>>(proj_b, x, out);

    // LN2
    ln_kernel<false><<<MROWS / 8, 256>>>(out, n2g, n2b);

    // FC1 + gelu
    gemm_f16<2048, 512, 2><<<dim3(2048 / 256, MROWS / 128), 256, SMEMB>>>(fc1_b, nullptr, nullptr);

    // FC2 + residual add into d_out
    gemm_f16<512, 2048, 3><<<dim3(512 / 256, MROWS / 128), 256, SMEMB>>>(fc2_b, nullptr, out);
}

// round 5
// speedup vs baseline: 1.2371x; 1.2371x over previous
#include <cuda_runtime.h>
#include <cuda_fp16.h>
#include <cstdint>

// ---------------- problem constants ----------------
#define DIMC   512
#define NHEADS 16
#define SSZ    4
#define BWIN   2048          // 32 batches * 64 windows
#define MROWS  131072        // BWIN * 64 == B*L
#define CHID   2048          // mlp hidden

// ---------------- scratch (device globals; no allocs allowed) ----------------
__device__ __half g_XN1[(size_t)MROWS * DIMC];
__device__ __half g_QKV[(size_t)MROWS * 3 * DIMC];
__device__ __half g_O  [(size_t)MROWS * DIMC];
__device__ __half g_XN2[(size_t)MROWS * DIMC];
__device__ __half g_H1 [(size_t)MROWS * CHID];
__device__ __half g_Wq [3 * DIMC * DIMC];
__device__ __half g_Wp [DIMC * DIMC];
__device__ __half g_W1 [CHID * DIMC];
__device__ __half g_W2 [DIMC * CHID];

#define NWQ (3 * DIMC * DIMC)
#define NWP (DIMC * DIMC)
#define NW1 (CHID * DIMC)
#define NW2 (DIMC * CHID)

// ---------------- helpers ----------------
__device__ __forceinline__ float gelu_f(float x) {
    return 0.5f * x * (1.0f + erff(x * 0.7071067811865475f));
}

__device__ __forceinline__ uint32_t smem_u32(const void* p) {
    return (uint32_t)__cvta_generic_to_shared(p);
}

// token index in window order -> token index in (B,H,W) order (shift mapping)
__device__ __forceinline__ size_t win_to_img(int t) {
    int b_   = t >> 6, nn = t & 63;
    int bimg = b_ >> 6, widx = b_ & 63;
    int gh = ((widx >> 3) << 3) + (nn >> 3);
    int gw = ((widx & 7) << 3) + (nn & 7);
    int sh = (gh + SSZ) & 63;
    int sw = (gw + SSZ) & 63;
    return ((size_t)bimg << 12) + (size_t)(sh << 6) + (size_t)sw;
}

#define LDSM_X4(r0, r1, r2, r3, addr)                                          \
    asm volatile("ldmatrix.sync.aligned.m8n8.x4.shared.b16 {%0,%1,%2,%3}, [%4];" \
                 : "=r"(r0), "=r"(r1), "=r"(r2), "=r"(r3) : "r"(addr))

#define MMA16816(d, a, b0, b1)                                                 \
    asm volatile(                                                              \
        "mma.sync.aligned.m16n8k16.row.col.f32.f16.f16.f32 "                   \
        "{%0,%1,%2,%3},{%4,%5,%6,%7},{%8,%9},{%0,%1,%2,%3};"                   \
        : "+f"((d)[0]), "+f"((d)[1]), "+f"((d)[2]), "+f"((d)[3])               \
        : "r"((a)[0]), "r"((a)[1]), "r"((a)[2]), "r"((a)[3]),                  \
          "r"(b0), "r"(b1))

// ---------------- weight convert (fp32 -> fp16), all 4 weights in one -------
__global__ void cvt_all(const float* __restrict__ wq, const float* __restrict__ wp,
                        const float* __restrict__ w1, const float* __restrict__ w2) {
    int i = blockIdx.x * 256 + threadIdx.x;
    if (i < NWQ) g_Wq[i] = __float2half(wq[i]);
    if (i < NWP) g_Wp[i] = __float2half(wp[i]);
    if (i < NW1) g_W1[i] = __float2half(w1[i]);
    if (i < NW2) g_W2[i] = __float2half(w2[i]);
}

// ---------------- layernorm (warp per token), optional shift+window remap ----
template <bool SHIFT>
__global__ void __launch_bounds__(256) ln_kernel(const float* __restrict__ xin,
                                                 const float* __restrict__ gamma,
                                                 const float* __restrict__ beta) {
    int t    = (blockIdx.x * 256 + threadIdx.x) >> 5;
    int lane = threadIdx.x & 31;
    __half* ob = SHIFT ? g_XN1 : g_XN2;

    size_t src = SHIFT ? win_to_img(t) : (size_t)t;
    const float* row = xin + src * DIMC;

    float4 v[4];
    float sum = 0.f, sq = 0.f;
#pragma unroll
    for (int p = 0; p < 4; p++) {
        v[p] = *(const float4*)(row + p * 128 + lane * 4);
        sum += v[p].x + v[p].y + v[p].z + v[p].w;
        sq  += v[p].x * v[p].x + v[p].y * v[p].y + v[p].z * v[p].z + v[p].w * v[p].w;
    }
#pragma unroll
    for (int o = 16; o > 0; o >>= 1) {
        sum += __shfl_xor_sync(0xffffffffu, sum, o);
        sq  += __shfl_xor_sync(0xffffffffu, sq, o);
    }
    float mu   = sum * (1.f / 512.f);
    float var  = sq * (1.f / 512.f) - mu * mu;
    float rstd = rsqrtf(var + 1e-5f);

    __half* orow = ob + (size_t)t * DIMC;
#pragma unroll
    for (int p = 0; p < 4; p++) {
        int c = p * 128 + lane * 4;
        float4 g4 = *(const float4*)(gamma + c);
        float4 b4 = *(const float4*)(beta + c);
        __half2 h0 = __floats2half2_rn((v[p].x - mu) * rstd * g4.x + b4.x,
                                       (v[p].y - mu) * rstd * g4.y + b4.y);
        __half2 h1 = __floats2half2_rn((v[p].z - mu) * rstd * g4.z + b4.z,
                                       (v[p].w - mu) * rstd * g4.w + b4.w);
        uint2 u;
        u.x = *(uint32_t*)&h0;
        u.y = *(uint32_t*)&h1;
        *(uint2*)(orow + c) = u;
    }
}

// ---------------- fp16 mma.sync GEMM: C[M,N] = A[M,K] @ W[N,K]^T ------------
// BM=128, BN=128, BK=64, 3-stage cp.async pipeline (2 tiles in flight),
// XOR-8 swizzle on 128B rows, 8 warps of 64x32, B frags via ldmatrix.x4,
// occupancy 2 enforced (regs <= 128).
// OP 0: -> g_QKV(f16) = acc + bias
// OP 1: -> out[remap] = aux[remap] + acc + bias   (fp32)
// OP 2: -> g_H1(f16) = gelu(acc + bias)
// OP 3: -> out += acc + bias                       (fp32)
template <int NTOT, int KTOT, int OP>
__global__ void __launch_bounds__(256, 2) gemm_f16(const float* __restrict__ bias,
                                                   const float* __restrict__ aux,
                                                   float* __restrict__ outp) {
    constexpr int BM = 128, BN = 128, BK = 64, STAGES = 3;
    constexpr int KT = KTOT / BK;
    constexpr uint32_t AB    = BM * BK * 2;   // 16KB
    constexpr uint32_t BB    = BN * BK * 2;   // 16KB
    constexpr uint32_t STAGE = AB + BB;       // 32KB

    extern __shared__ char smem[];
    const uint32_t sbase = smem_u32(smem);
    const int tid = threadIdx.x;

    const __half* A;
    const __half* Bw;
    if (OP == 0)      { A = g_XN1; Bw = g_Wq; }
    else if (OP == 1) { A = g_O;   Bw = g_Wp; }
    else if (OP == 2) { A = g_XN2; Bw = g_W1; }
    else              { A = g_H1;  Bw = g_W2; }

    const int m0 = blockIdx.y * BM;
    const int n0 = blockIdx.x * BN;

    // 128 rows x 8 chunks (16B) per operand; 1024 chunks / 256 threads = 4 iters
    auto load_tile = [&](int kt, int s) {
        const __half* gA = A + (size_t)m0 * KTOT + kt * BK;
        const __half* gB = Bw + (size_t)n0 * KTOT + kt * BK;
#pragma unroll
        for (int i = 0; i < 4; i++) {
            int idx = i * 256 + tid;
            int r = idx >> 3, g = idx & 7;
            uint32_t off = (uint32_t)(r * 128 + ((g ^ (r & 7)) << 4));
            uint32_t da = sbase + (uint32_t)s * STAGE + off;
            const __half* pa = gA + (size_t)r * KTOT + g * 8;
            asm volatile("cp.async.cg.shared.global [%0], [%1], 16;\n" ::"r"(da), "l"(pa));
            uint32_t db = sbase + (uint32_t)s * STAGE + AB + off;
            const __half* pb = gB + (size_t)r * KTOT + g * 8;
            asm volatile("cp.async.cg.shared.global [%0], [%1], 16;\n" ::"r"(db), "l"(pb));
        }
        asm volatile("cp.async.commit_group;\n");
    };

    const int w    = tid >> 5;
    const int wm   = w >> 2;    // 0..1 (64 rows)
    const int wn   = w & 3;     // 0..3 (32 cols)
    const int lane = tid & 31;
    const int grp  = lane >> 2;
    const int tig  = lane & 3;

    float acc[4][4][4];
#pragma unroll
    for (int i = 0; i < 4; i++)
#pragma unroll
        for (int j = 0; j < 4; j++)
#pragma unroll
            for (int r = 0; r < 4; r++) acc[i][j][r] = 0.f;

    // ldmatrix lane addressing
    const int a_row  = wm * 64 + (lane & 15);                     // + mt*16
    const int a_chk0 = lane >> 4;                                  // + ks*2
    const int b_row  = wn * 32 + (lane & 7) + ((lane >> 4) << 3);  // + nt2*16
    const int b_chk0 = (lane >> 3) & 1;                            // + ks*2

    load_tile(0, 0);
    load_tile(1, 1);

#pragma unroll 1
    for (int kt = 0; kt < KT; ++kt) {
        if (kt + 2 < KT) asm volatile("cp.async.wait_group 1;\n");
        else             asm volatile("cp.async.wait_group 0;\n");
        __syncthreads();

        if (kt + 2 < KT) load_tile(kt + 2, (kt + 2) % STAGES);

        const uint32_t stA = sbase + (uint32_t)(kt % STAGES) * STAGE;
        const uint32_t stB = stA + AB;

#pragma unroll
        for (int ks = 0; ks < 4; ++ks) {
            uint32_t a[4][4], b[2][4];
#pragma unroll
            for (int mt = 0; mt < 4; ++mt) {
                int r = a_row + mt * 16;
                int c = ks * 2 + a_chk0;
                uint32_t ad = stA + (uint32_t)(r * 128 + ((c ^ (r & 7)) << 4));
                LDSM_X4(a[mt][0], a[mt][1], a[mt][2], a[mt][3], ad);
            }
#pragma unroll
            for (int nt2 = 0; nt2 < 2; ++nt2) {
                int r = b_row + nt2 * 16;
                int c = ks * 2 + b_chk0;
                uint32_t bd = stB + (uint32_t)(r * 128 + ((c ^ (r & 7)) << 4));
                LDSM_X4(b[nt2][0], b[nt2][1], b[nt2][2], b[nt2][3], bd);
            }
#pragma unroll
            for (int mt = 0; mt < 4; ++mt)
#pragma unroll
                for (int nt = 0; nt < 4; ++nt)
                    MMA16816(acc[mt][nt], a[mt], b[nt >> 1][(nt & 1) * 2], b[nt >> 1][(nt & 1) * 2 + 1]);
        }
    }

    // ---- epilogue ----
#pragma unroll
    for (int mt = 0; mt < 4; ++mt) {
        int r_lo = m0 + wm * 64 + mt * 16 + grp;
        int r_hi = r_lo + 8;
        size_t d_lo = 0, d_hi = 0;
        if (OP == 1) {
            d_lo = win_to_img(r_lo) * DIMC;
            d_hi = win_to_img(r_hi) * DIMC;
        }
#pragma unroll
        for (int nt = 0; nt < 4; ++nt) {
            int c0 = n0 + wn * 32 + nt * 8 + 2 * tig;
            float b0 = bias[c0], b1 = bias[c0 + 1];
            float v00 = acc[mt][nt][0] + b0;
            float v01 = acc[mt][nt][1] + b1;
            float v10 = acc[mt][nt][2] + b0;
            float v11 = acc[mt][nt][3] + b1;
            if (OP == 0) {
                *(__half2*)(g_QKV + (size_t)r_lo * NTOT + c0) = __floats2half2_rn(v00, v01);
                *(__half2*)(g_QKV + (size_t)r_hi * NTOT + c0) = __floats2half2_rn(v10, v11);
            } else if (OP == 1) {
                float2 a0 = *(const float2*)(aux + d_lo + c0);
                float2 a1 = *(const float2*)(aux + d_hi + c0);
                *(float2*)(outp + d_lo + c0) = make_float2(a0.x + v00, a0.y + v01);
                *(float2*)(outp + d_hi + c0) = make_float2(a1.x + v10, a1.y + v11);
            } else if (OP == 2) {
                *(__half2*)(g_H1 + (size_t)r_lo * NTOT + c0) =
                    __floats2half2_rn(gelu_f(v00), gelu_f(v01));
                *(__half2*)(g_H1 + (size_t)r_hi * NTOT + c0) =
                    __floats2half2_rn(gelu_f(v10), gelu_f(v11));
            } else {
                size_t o0 = (size_t)r_lo * NTOT + c0;
                size_t o1 = (size_t)r_hi * NTOT + c0;
                float2 p0 = *(const float2*)(outp + o0);
                float2 p1 = *(const float2*)(outp + o1);
                *(float2*)(outp + o0) = make_float2(p0.x + v00, p0.y + v01);
                *(float2*)(outp + o1) = make_float2(p1.x + v10, p1.y + v11);
            }
        }
    }
}

// ---------------- attention: one block per (window, head) -------------------
__global__ void __launch_bounds__(64) attn_kernel(const float* __restrict__ rpb) {
    __shared__ float sk[64][36];
    __shared__ float sv[64][36];
    __shared__ float srpb[225];
    __shared__ int   slab[64];

    int bh = blockIdx.x;
    int b_ = bh >> 4;
    int h  = bh & 15;
    int n  = threadIdx.x;

    const __half* qkvrow = g_QKV + (size_t)(b_ * 64 + n) * (3 * DIMC) + h * 32;

    float q[32];
#pragma unroll
    for (int j = 0; j < 4; j++) {
        uint4 u = *(const uint4*)(qkvrow + j * 8);
        const __half2* hp = (const __half2*)&u;
#pragma unroll
        for (int e = 0; e < 4; e++) {
            float2 f = __half22float2(hp[e]);
            q[j * 8 + e * 2]     = f.x;
            q[j * 8 + e * 2 + 1] = f.y;
        }
    }
#pragma unroll
    for (int j = 0; j < 4; j++) {
        uint4 u = *(const uint4*)(qkvrow + DIMC + j * 8);
        const __half2* hp = (const __half2*)&u;
#pragma unroll
        for (int e = 0; e < 4; e++) {
            float2 f = __half22float2(hp[e]);
            sk[n][j * 8 + e * 2]     = f.x;
            sk[n][j * 8 + e * 2 + 1] = f.y;
        }
    }
#pragma unroll
    for (int j = 0; j < 4; j++) {
        uint4 u = *(const uint4*)(qkvrow + 2 * DIMC + j * 8);
        const __half2* hp = (const __half2*)&u;
#pragma unroll
        for (int e = 0; e < 4; e++) {
            float2 f = __half22float2(hp[e]);
            sv[n][j * 8 + e * 2]     = f.x;
            sv[n][j * 8 + e * 2 + 1] = f.y;
        }
    }

    for (int i = n; i < 225; i += 64) srpb[i] = rpb[i * NHEADS + h];

    {
        int widx = b_ & 63;
        int gh = ((widx >> 3) << 3) + (n >> 3);
        int gw = ((widx & 7) << 3) + (n & 7);
        int zh = gh < 56 ? 0 : (gh < 60 ? 1 : 2);
        int zw = gw < 56 ? 0 : (gw < 60 ? 1 : 2);
        slab[n] = zh * 3 + zw;
    }
    __syncthreads();

    const float scale = 0.17677669529663687f;  // 1/sqrt(32)
    int   mylab = slab[n];
    int   rh = n >> 3, rw = n & 7;

    float s[64];
#pragma unroll
    for (int m = 0; m < 64; m++) {
        float a0 = 0.f, a1 = 0.f, a2 = 0.f, a3 = 0.f;
#pragma unroll
        for (int j = 0; j < 8; j++) {
            float4 kk = *(const float4*)&sk[m][j * 4];
            a0 += q[j * 4]     * kk.x;
            a1 += q[j * 4 + 1] * kk.y;
            a2 += q[j * 4 + 2] * kk.z;
            a3 += q[j * 4 + 3] * kk.w;
        }
        int idx = (rh - (m >> 3) + 7) * 15 + (rw - (m & 7) + 7);
        float msk = (mylab == slab[m]) ? 0.f : -100.f;
        s[m] = ((a0 + a1) + (a2 + a3)) * scale + srpb[idx] + msk;
    }

    float mx = -1e30f;
#pragma unroll
    for (int m = 0; m < 64; m++) mx = fmaxf(mx, s[m]);
    float sum = 0.f;
#pragma unroll
    for (int m = 0; m < 64; m++) {
        s[m] = __expf(s[m] - mx);
        sum += s[m];
    }
    float inv = 1.f / sum;

    float o[32];
#pragma unroll
    for (int d = 0; d < 32; d++) o[d] = 0.f;
#pragma unroll
    for (int m = 0; m < 64; m++) {
        float p = s[m] * inv;
#pragma unroll
        for (int j = 0; j < 8; j++) {
            float4 vv = *(const float4*)&sv[m][j * 4];
            o[j * 4]     += p * vv.x;
            o[j * 4 + 1] += p * vv.y;
            o[j * 4 + 2] += p * vv.z;
            o[j * 4 + 3] += p * vv.w;
        }
    }

    __half* orow = g_O + (size_t)(b_ * 64 + n) * DIMC + h * 32;
#pragma unroll
    for (int j = 0; j < 4; j++) {
        __half2 h0 = __floats2half2_rn(o[j * 8],     o[j * 8 + 1]);
        __half2 h1 = __floats2half2_rn(o[j * 8 + 2], o[j * 8 + 3]);
        __half2 h2 = __floats2half2_rn(o[j * 8 + 4], o[j * 8 + 5]);
        __half2 h3 = __floats2half2_rn(o[j * 8 + 6], o[j * 8 + 7]);
        uint4 u;
        u.x = *(uint32_t*)&h0;
        u.y = *(uint32_t*)&h1;
        u.z = *(uint32_t*)&h2;
        u.w = *(uint32_t*)&h3;
        *(uint4*)(orow + j * 8) = u;
    }
}

// ---------------- host launcher ----------------
extern "C" void kernel_launch(void* const* d_in, const int* in_sizes, int n_in,
                              void* d_out, int out_size) {
    const float* x      = (const float*)d_in[0];
    const float* n1g    = (const float*)d_in[1];
    const float* n1b    = (const float*)d_in[2];
    const float* qkv_w  = (const float*)d_in[3];
    const float* qkv_b  = (const float*)d_in[4];
    const float* proj_w = (const float*)d_in[5];
    const float* proj_b = (const float*)d_in[6];
    const float* rpb    = (const float*)d_in[7];
    const float* n2g    = (const float*)d_in[8];
    const float* n2b    = (const float*)d_in[9];
    const float* fc1_w  = (const float*)d_in[10];
    const float* fc1_b  = (const float*)d_in[11];
    const float* fc2_w  = (const float*)d_in[12];
    const float* fc2_b  = (const float*)d_in[13];
    float* out = (float*)d_out;

    constexpr int SMEMB = 3 * (128 * 64 * 2 + 128 * 64 * 2);  // 98304 bytes

    cudaFuncSetAttribute(gemm_f16<1536, 512, 0>, cudaFuncAttributeMaxDynamicSharedMemorySize, SMEMB);
    cudaFuncSetAttribute(gemm_f16<512,  512, 1>, cudaFuncAttributeMaxDynamicSharedMemorySize, SMEMB);
    cudaFuncSetAttribute(gemm_f16<2048, 512, 2>, cudaFuncAttributeMaxDynamicSharedMemorySize, SMEMB);
    cudaFuncSetAttribute(gemm_f16<512, 2048, 3>, cudaFuncAttributeMaxDynamicSharedMemorySize, SMEMB);

    // weights -> fp16 copies (single kernel)
    cvt_all<<<(NW1 + 255) / 256, 256>>>(qkv_w, proj_w, fc1_w, fc2_w);

    // LN1 + shift + window partition
    ln_kernel<true><<<MROWS / 8, 256>>>(x, n1g, n1b);

    // QKV projection
    gemm_f16<1536, 512, 0><<<dim3(1536 / 128, MROWS / 128), 256, SMEMB>>>(qkv_b, nullptr, nullptr);

    // windowed attention
    attn_kernel<<<BWIN * NHEADS, 64>>>(rpb);

    // output projection + window reverse + shift + residual -> d_out
    gemm_f16<512, 512, 1><<<dim3(512 / 128, MROWS / 128), 256, SMEMB>>>(proj_b, x, out);

    // LN2
    ln_kernel<false><<<MROWS / 8, 256>>>(out, n2g, n2b);

    // FC1 + gelu
    gemm_f16<2048, 512, 2><<<dim3(2048 / 128, MROWS / 128), 256, SMEMB>>>(fc1_b, nullptr, nullptr);

    // FC2 + residual add into d_out
    gemm_f16<512, 2048, 3><<<dim3(512 / 128, MROWS / 128), 256, SMEMB>>>(fc2_b, nullptr, out);
}

// round 6
// speedup vs baseline: 1.2504x; 1.0107x over previous
#include <cuda_runtime.h>
#include <cuda_fp16.h>
#include <cstdint>

// ---------------- problem constants ----------------
#define DIMC   512
#define NHEADS 16
#define SSZ    4
#define BWIN   2048          // 32 batches * 64 windows
#define MROWS  131072        // BWIN * 64 == B*L
#define CHID   2048          // mlp hidden

// ---------------- scratch (device globals; no allocs allowed) ----------------
__device__ __half g_XN1[(size_t)MROWS * DIMC];
__device__ __half g_QKV[(size_t)MROWS * 3 * DIMC];
__device__ __half g_O  [(size_t)MROWS * DIMC];
__device__ __half g_XN2[(size_t)MROWS * DIMC];
__device__ __half g_H1 [(size_t)MROWS * CHID];
__device__ __half g_Wq [3 * DIMC * DIMC];
__device__ __half g_Wp [DIMC * DIMC];
__device__ __half g_W1 [CHID * DIMC];
__device__ __half g_W2 [DIMC * CHID];

#define NWQ (3 * DIMC * DIMC)
#define NWP (DIMC * DIMC)
#define NW1 (CHID * DIMC)
#define NW2 (DIMC * CHID)

// ---------------- helpers ----------------
__device__ __forceinline__ float gelu_f(float x) {
    return 0.5f * x * (1.0f + erff(x * 0.7071067811865475f));
}

__device__ __forceinline__ uint32_t smem_u32(const void* p) {
    return (uint32_t)__cvta_generic_to_shared(p);
}

// token index in window order -> token index in (B,H,W) order (shift mapping)
__device__ __forceinline__ size_t win_to_img(int t) {
    int b_   = t >> 6, nn = t & 63;
    int bimg = b_ >> 6, widx = b_ & 63;
    int gh = ((widx >> 3) << 3) + (nn >> 3);
    int gw = ((widx & 7) << 3) + (nn & 7);
    int sh = (gh + SSZ) & 63;
    int sw = (gw + SSZ) & 63;
    return ((size_t)bimg << 12) + (size_t)(sh << 6) + (size_t)sw;
}

#define LDSM_X4(r0, r1, r2, r3, addr)                                          \
    asm volatile("ldmatrix.sync.aligned.m8n8.x4.shared.b16 {%0,%1,%2,%3}, [%4];" \
                 : "=r"(r0), "=r"(r1), "=r"(r2), "=r"(r3) : "r"(addr))

#define MMA16816(d, a, b0, b1)                                                 \
    asm volatile(                                                              \
        "mma.sync.aligned.m16n8k16.row.col.f32.f16.f16.f32 "                   \
        "{%0,%1,%2,%3},{%4,%5,%6,%7},{%8,%9},{%0,%1,%2,%3};"                   \
        : "+f"((d)[0]), "+f"((d)[1]), "+f"((d)[2]), "+f"((d)[3])               \
        : "r"((a)[0]), "r"((a)[1]), "r"((a)[2]), "r"((a)[3]),                  \
          "r"(b0), "r"(b1))

// ---------------- weight convert (fp32 -> fp16), all 4 weights in one -------
__global__ void cvt_all(const float* __restrict__ wq, const float* __restrict__ wp,
                        const float* __restrict__ w1, const float* __restrict__ w2) {
    int i = blockIdx.x * 256 + threadIdx.x;
    if (i < NWQ) g_Wq[i] = __float2half(wq[i]);
    if (i < NWP) g_Wp[i] = __float2half(wp[i]);
    if (i < NW1) g_W1[i] = __float2half(w1[i]);
    if (i < NW2) g_W2[i] = __float2half(w2[i]);
}

// ---------------- layernorm (warp per token), optional shift+window remap ----
template <bool SHIFT>
__global__ void __launch_bounds__(256) ln_kernel(const float* __restrict__ xin,
                                                 const float* __restrict__ gamma,
                                                 const float* __restrict__ beta) {
    int t    = (blockIdx.x * 256 + threadIdx.x) >> 5;
    int lane = threadIdx.x & 31;
    __half* ob = SHIFT ? g_XN1 : g_XN2;

    size_t src = SHIFT ? win_to_img(t) : (size_t)t;
    const float* row = xin + src * DIMC;

    float4 v[4];
    float sum = 0.f, sq = 0.f;
#pragma unroll
    for (int p = 0; p < 4; p++) {
        v[p] = *(const float4*)(row + p * 128 + lane * 4);
        sum += v[p].x + v[p].y + v[p].z + v[p].w;
        sq  += v[p].x * v[p].x + v[p].y * v[p].y + v[p].z * v[p].z + v[p].w * v[p].w;
    }
#pragma unroll
    for (int o = 16; o > 0; o >>= 1) {
        sum += __shfl_xor_sync(0xffffffffu, sum, o);
        sq  += __shfl_xor_sync(0xffffffffu, sq, o);
    }
    float mu   = sum * (1.f / 512.f);
    float var  = sq * (1.f / 512.f) - mu * mu;
    float rstd = rsqrtf(var + 1e-5f);

    __half* orow = ob + (size_t)t * DIMC;
#pragma unroll
    for (int p = 0; p < 4; p++) {
        int c = p * 128 + lane * 4;
        float4 g4 = *(const float4*)(gamma + c);
        float4 b4 = *(const float4*)(beta + c);
        __half2 h0 = __floats2half2_rn((v[p].x - mu) * rstd * g4.x + b4.x,
                                       (v[p].y - mu) * rstd * g4.y + b4.y);
        __half2 h1 = __floats2half2_rn((v[p].z - mu) * rstd * g4.z + b4.z,
                                       (v[p].w - mu) * rstd * g4.w + b4.w);
        uint2 u;
        u.x = *(uint32_t*)&h0;
        u.y = *(uint32_t*)&h1;
        *(uint2*)(orow + c) = u;
    }
}

// ---------------- fp16 mma.sync GEMM: C[M,N] = A[M,K] @ W[N,K]^T ------------
// BM=128, BN=128, BK=64, 3-stage cp.async pipeline (2 tiles in flight),
// XOR-8 swizzle on 128B rows, 8 warps of 64x32, B frags via ldmatrix.x4,
// occupancy 2 enforced (regs <= 128).
template <int NTOT, int KTOT, int OP>
__global__ void __launch_bounds__(256, 2) gemm_f16(const float* __restrict__ bias,
                                                   const float* __restrict__ aux,
                                                   float* __restrict__ outp) {
    constexpr int BM = 128, BN = 128, BK = 64, STAGES = 3;
    constexpr int KT = KTOT / BK;
    constexpr uint32_t AB    = BM * BK * 2;   // 16KB
    constexpr uint32_t BB    = BN * BK * 2;   // 16KB
    constexpr uint32_t STAGE = AB + BB;       // 32KB

    extern __shared__ char smem[];
    const uint32_t sbase = smem_u32(smem);
    const int tid = threadIdx.x;

    const __half* A;
    const __half* Bw;
    if (OP == 0)      { A = g_XN1; Bw = g_Wq; }
    else if (OP == 1) { A = g_O;   Bw = g_Wp; }
    else if (OP == 2) { A = g_XN2; Bw = g_W1; }
    else              { A = g_H1;  Bw = g_W2; }

    const int m0 = blockIdx.y * BM;
    const int n0 = blockIdx.x * BN;

    // 128 rows x 8 chunks (16B) per operand; 1024 chunks / 256 threads = 4 iters
    auto load_tile = [&](int kt, int s) {
        const __half* gA = A + (size_t)m0 * KTOT + kt * BK;
        const __half* gB = Bw + (size_t)n0 * KTOT + kt * BK;
#pragma unroll
        for (int i = 0; i < 4; i++) {
            int idx = i * 256 + tid;
            int r = idx >> 3, g = idx & 7;
            uint32_t off = (uint32_t)(r * 128 + ((g ^ (r & 7)) << 4));
            uint32_t da = sbase + (uint32_t)s * STAGE + off;
            const __half* pa = gA + (size_t)r * KTOT + g * 8;
            asm volatile("cp.async.cg.shared.global [%0], [%1], 16;\n" ::"r"(da), "l"(pa));
            uint32_t db = sbase + (uint32_t)s * STAGE + AB + off;
            const __half* pb = gB + (size_t)r * KTOT + g * 8;
            asm volatile("cp.async.cg.shared.global [%0], [%1], 16;\n" ::"r"(db), "l"(pb));
        }
        asm volatile("cp.async.commit_group;\n");
    };

    const int w    = tid >> 5;
    const int wm   = w >> 2;    // 0..1 (64 rows)
    const int wn   = w & 3;     // 0..3 (32 cols)
    const int lane = tid & 31;
    const int grp  = lane >> 2;
    const int tig  = lane & 3;

    float acc[4][4][4];
#pragma unroll
    for (int i = 0; i < 4; i++)
#pragma unroll
        for (int j = 0; j < 4; j++)
#pragma unroll
            for (int r = 0; r < 4; r++) acc[i][j][r] = 0.f;

    // ldmatrix lane addressing
    const int a_row  = wm * 64 + (lane & 15);                     // + mt*16
    const int a_chk0 = lane >> 4;                                  // + ks*2
    const int b_row  = wn * 32 + (lane & 7) + ((lane >> 4) << 3);  // + nt2*16
    const int b_chk0 = (lane >> 3) & 1;                            // + ks*2

    load_tile(0, 0);
    load_tile(1, 1);

#pragma unroll 1
    for (int kt = 0; kt < KT; ++kt) {
        if (kt + 2 < KT) asm volatile("cp.async.wait_group 1;\n");
        else             asm volatile("cp.async.wait_group 0;\n");
        __syncthreads();

        if (kt + 2 < KT) load_tile(kt + 2, (kt + 2) % STAGES);

        const uint32_t stA = sbase + (uint32_t)(kt % STAGES) * STAGE;
        const uint32_t stB = stA + AB;

#pragma unroll
        for (int ks = 0; ks < 4; ++ks) {
            uint32_t a[4][4], b[2][4];
#pragma unroll
            for (int mt = 0; mt < 4; ++mt) {
                int r = a_row + mt * 16;
                int c = ks * 2 + a_chk0;
                uint32_t ad = stA + (uint32_t)(r * 128 + ((c ^ (r & 7)) << 4));
                LDSM_X4(a[mt][0], a[mt][1], a[mt][2], a[mt][3], ad);
            }
#pragma unroll
            for (int nt2 = 0; nt2 < 2; ++nt2) {
                int r = b_row + nt2 * 16;
                int c = ks * 2 + b_chk0;
                uint32_t bd = stB + (uint32_t)(r * 128 + ((c ^ (r & 7)) << 4));
                LDSM_X4(b[nt2][0], b[nt2][1], b[nt2][2], b[nt2][3], bd);
            }
#pragma unroll
            for (int mt = 0; mt < 4; ++mt)
#pragma unroll
                for (int nt = 0; nt < 4; ++nt)
                    MMA16816(acc[mt][nt], a[mt], b[nt >> 1][(nt & 1) * 2], b[nt >> 1][(nt & 1) * 2 + 1]);
        }
    }

    // ---- epilogue ----
#pragma unroll
    for (int mt = 0; mt < 4; ++mt) {
        int r_lo = m0 + wm * 64 + mt * 16 + grp;
        int r_hi = r_lo + 8;
        size_t d_lo = 0, d_hi = 0;
        if (OP == 1) {
            d_lo = win_to_img(r_lo) * DIMC;
            d_hi = win_to_img(r_hi) * DIMC;
        }
#pragma unroll
        for (int nt = 0; nt < 4; ++nt) {
            int c0 = n0 + wn * 32 + nt * 8 + 2 * tig;
            float b0 = bias[c0], b1 = bias[c0 + 1];
            float v00 = acc[mt][nt][0] + b0;
            float v01 = acc[mt][nt][1] + b1;
            float v10 = acc[mt][nt][2] + b0;
            float v11 = acc[mt][nt][3] + b1;
            if (OP == 0) {
                *(__half2*)(g_QKV + (size_t)r_lo * NTOT + c0) = __floats2half2_rn(v00, v01);
                *(__half2*)(g_QKV + (size_t)r_hi * NTOT + c0) = __floats2half2_rn(v10, v11);
            } else if (OP == 1) {
                float2 a0 = *(const float2*)(aux + d_lo + c0);
                float2 a1 = *(const float2*)(aux + d_hi + c0);
                *(float2*)(outp + d_lo + c0) = make_float2(a0.x + v00, a0.y + v01);
                *(float2*)(outp + d_hi + c0) = make_float2(a1.x + v10, a1.y + v11);
            } else if (OP == 2) {
                *(__half2*)(g_H1 + (size_t)r_lo * NTOT + c0) =
                    __floats2half2_rn(gelu_f(v00), gelu_f(v01));
                *(__half2*)(g_H1 + (size_t)r_hi * NTOT + c0) =
                    __floats2half2_rn(gelu_f(v10), gelu_f(v11));
            } else {
                size_t o0 = (size_t)r_lo * NTOT + c0;
                size_t o1 = (size_t)r_hi * NTOT + c0;
                float2 p0 = *(const float2*)(outp + o0);
                float2 p1 = *(const float2*)(outp + o1);
                *(float2*)(outp + o0) = make_float2(p0.x + v00, p0.y + v01);
                *(float2*)(outp + o1) = make_float2(p1.x + v10, p1.y + v11);
            }
        }
    }
}

// ---------------- attention: one block per (window, head) -------------------
// Single-pass softmax (no max subtraction — scores bounded; masked lanes
// underflow exp() to 0 which matches the -100 mask semantics within 1e-3).
// Registers ~90 (no s[64] array) -> ~2x occupancy vs two-pass version.
__global__ void __launch_bounds__(64) attn_kernel(const float* __restrict__ rpb) {
    __shared__ float sk[64][36];
    __shared__ float sv[64][36];
    __shared__ float srpb[225];
    __shared__ int   slab[64];

    int bh = blockIdx.x;
    int b_ = bh >> 4;
    int h  = bh & 15;
    int n  = threadIdx.x;

    const __half* qkvrow = g_QKV + (size_t)(b_ * 64 + n) * (3 * DIMC) + h * 32;

    float q[32];
#pragma unroll
    for (int j = 0; j < 4; j++) {
        uint4 u = *(const uint4*)(qkvrow + j * 8);
        const __half2* hp = (const __half2*)&u;
#pragma unroll
        for (int e = 0; e < 4; e++) {
            float2 f = __half22float2(hp[e]);
            q[j * 8 + e * 2]     = f.x;
            q[j * 8 + e * 2 + 1] = f.y;
        }
    }
#pragma unroll
    for (int j = 0; j < 4; j++) {
        uint4 u = *(const uint4*)(qkvrow + DIMC + j * 8);
        const __half2* hp = (const __half2*)&u;
#pragma unroll
        for (int e = 0; e < 4; e++) {
            float2 f = __half22float2(hp[e]);
            sk[n][j * 8 + e * 2]     = f.x;
            sk[n][j * 8 + e * 2 + 1] = f.y;
        }
    }
#pragma unroll
    for (int j = 0; j < 4; j++) {
        uint4 u = *(const uint4*)(qkvrow + 2 * DIMC + j * 8);
        const __half2* hp = (const __half2*)&u;
#pragma unroll
        for (int e = 0; e < 4; e++) {
            float2 f = __half22float2(hp[e]);
            sv[n][j * 8 + e * 2]     = f.x;
            sv[n][j * 8 + e * 2 + 1] = f.y;
        }
    }

    for (int i = n; i < 225; i += 64) srpb[i] = rpb[i * NHEADS + h];

    {
        int widx = b_ & 63;
        int gh = ((widx >> 3) << 3) + (n >> 3);
        int gw = ((widx & 7) << 3) + (n & 7);
        int zh = gh < 56 ? 0 : (gh < 60 ? 1 : 2);
        int zw = gw < 56 ? 0 : (gw < 60 ? 1 : 2);
        slab[n] = zh * 3 + zw;
    }
    __syncthreads();

    const float scale = 0.17677669529663687f;  // 1/sqrt(32)
    int   mylab = slab[n];
    int   rh = n >> 3, rw = n & 7;

    float o[32];
#pragma unroll
    for (int d = 0; d < 32; d++) o[d] = 0.f;
    float sum = 0.f;

#pragma unroll 4
    for (int m = 0; m < 64; m++) {
        float a0 = 0.f, a1 = 0.f, a2 = 0.f, a3 = 0.f;
#pragma unroll
        for (int j = 0; j < 8; j++) {
            float4 kk = *(const float4*)&sk[m][j * 4];
            a0 += q[j * 4]     * kk.x;
            a1 += q[j * 4 + 1] * kk.y;
            a2 += q[j * 4 + 2] * kk.z;
            a3 += q[j * 4 + 3] * kk.w;
        }
        int idx = (rh - (m >> 3) + 7) * 15 + (rw - (m & 7) + 7);
        float msk = (mylab == slab[m]) ? 0.f : -100.f;
        float s = ((a0 + a1) + (a2 + a3)) * scale + srpb[idx] + msk;
        float e = __expf(s);
        sum += e;
#pragma unroll
        for (int j = 0; j < 8; j++) {
            float4 vv = *(const float4*)&sv[m][j * 4];
            o[j * 4]     += e * vv.x;
            o[j * 4 + 1] += e * vv.y;
            o[j * 4 + 2] += e * vv.z;
            o[j * 4 + 3] += e * vv.w;
        }
    }

    float inv = 1.f / sum;

    __half* orow = g_O + (size_t)(b_ * 64 + n) * DIMC + h * 32;
#pragma unroll
    for (int j = 0; j < 4; j++) {
        __half2 h0 = __floats2half2_rn(o[j * 8]     * inv, o[j * 8 + 1] * inv);
        __half2 h1 = __floats2half2_rn(o[j * 8 + 2] * inv, o[j * 8 + 3] * inv);
        __half2 h2 = __floats2half2_rn(o[j * 8 + 4] * inv, o[j * 8 + 5] * inv);
        __half2 h3 = __floats2half2_rn(o[j * 8 + 6] * inv, o[j * 8 + 7] * inv);
        uint4 u;
        u.x = *(uint32_t*)&h0;
        u.y = *(uint32_t*)&h1;
        u.z = *(uint32_t*)&h2;
        u.w = *(uint32_t*)&h3;
        *(uint4*)(orow + j * 8) = u;
    }
}

// ---------------- host launcher ----------------
extern "C" void kernel_launch(void* const* d_in, const int* in_sizes, int n_in,
                              void* d_out, int out_size) {
    const float* x      = (const float*)d_in[0];
    const float* n1g    = (const float*)d_in[1];
    const float* n1b    = (const float*)d_in[2];
    const float* qkv_w  = (const float*)d_in[3];
    const float* qkv_b  = (const float*)d_in[4];
    const float* proj_w = (const float*)d_in[5];
    const float* proj_b = (const float*)d_in[6];
    const float* rpb    = (const float*)d_in[7];
    const float* n2g    = (const float*)d_in[8];
    const float* n2b    = (const float*)d_in[9];
    const float* fc1_w  = (const float*)d_in[10];
    const float* fc1_b  = (const float*)d_in[11];
    const float* fc2_w  = (const float*)d_in[12];
    const float* fc2_b  = (const float*)d_in[13];
    float* out = (float*)d_out;

    constexpr int SMEMB = 3 * (128 * 64 * 2 + 128 * 64 * 2);  // 98304 bytes

    cudaFuncSetAttribute(gemm_f16<1536, 512, 0>, cudaFuncAttributeMaxDynamicSharedMemorySize, SMEMB);
    cudaFuncSetAttribute(gemm_f16<512,  512, 1>, cudaFuncAttributeMaxDynamicSharedMemorySize, SMEMB);
    cudaFuncSetAttribute(gemm_f16<2048, 512, 2>, cudaFuncAttributeMaxDynamicSharedMemorySize, SMEMB);
    cudaFuncSetAttribute(gemm_f16<512, 2048, 3>, cudaFuncAttributeMaxDynamicSharedMemorySize, SMEMB);

    // weights -> fp16 copies (single kernel)
    cvt_all<<<(NW1 + 255) / 256, 256>>>(qkv_w, proj_w, fc1_w, fc2_w);

    // LN1 + shift + window partition
    ln_kernel<true><<<MROWS / 8, 256>>>(x, n1g, n1b);

    // QKV projection
    gemm_f16<1536, 512, 0><<<dim3(1536 / 128, MROWS / 128), 256, SMEMB>>>(qkv_b, nullptr, nullptr);

    // windowed attention
    attn_kernel<<<BWIN * NHEADS, 64>>>(rpb);

    // output projection + window reverse + shift + residual -> d_out
    gemm_f16<512, 512, 1><<<dim3(512 / 128, MROWS / 128), 256, SMEMB>>>(proj_b, x, out);

    // LN2
    ln_kernel<false><<<MROWS / 8, 256>>>(out, n2g, n2b);

    // FC1 + gelu
    gemm_f16<2048, 512, 2><<<dim3(2048 / 128, MROWS / 128), 256, SMEMB>>>(fc1_b, nullptr, nullptr);

    // FC2 + residual add into d_out
    gemm_f16<512, 2048, 3><<<dim3(512 / 128, MROWS / 128), 256, SMEMB>>>(fc2_b, nullptr, out);
}

// round 7
// speedup vs baseline: 1.4865x; 1.1888x over previous
#include <cuda_runtime.h>
#include <cuda_fp16.h>
#include <cstdint>

// ---------------- problem constants ----------------
#define DIMC   512
#define NHEADS 16
#define SSZ    4
#define BWIN   2048          // 32 batches * 64 windows
#define MROWS  131072        // BWIN * 64 == B*L
#define CHID   2048          // mlp hidden

// ---------------- scratch (device globals; no allocs allowed) ----------------
__device__ __half g_XN1[(size_t)MROWS * DIMC];
__device__ __half g_QKV[(size_t)MROWS * 3 * DIMC];
__device__ __half g_O  [(size_t)MROWS * DIMC];
__device__ __half g_XN2[(size_t)MROWS * DIMC];
__device__ __half g_H1 [(size_t)MROWS * CHID];
__device__ __half g_Wq [3 * DIMC * DIMC];
__device__ __half g_Wp [DIMC * DIMC];
__device__ __half g_W1 [CHID * DIMC];
__device__ __half g_W2 [DIMC * CHID];

#define NWQ (3 * DIMC * DIMC)
#define NWP (DIMC * DIMC)
#define NW1 (CHID * DIMC)
#define NW2 (DIMC * CHID)

// ---------------- helpers ----------------
__device__ __forceinline__ float gelu_f(float x) {
    return 0.5f * x * (1.0f + erff(x * 0.7071067811865475f));
}

__device__ __forceinline__ uint32_t smem_u32(const void* p) {
    return (uint32_t)__cvta_generic_to_shared(p);
}

// token index in window order -> token index in (B,H,W) order (shift mapping)
__device__ __forceinline__ size_t win_to_img(int t) {
    int b_   = t >> 6, nn = t & 63;
    int bimg = b_ >> 6, widx = b_ & 63;
    int gh = ((widx >> 3) << 3) + (nn >> 3);
    int gw = ((widx & 7) << 3) + (nn & 7);
    int sh = (gh + SSZ) & 63;
    int sw = (gw + SSZ) & 63;
    return ((size_t)bimg << 12) + (size_t)(sh << 6) + (size_t)sw;
}

#define LDSM_X4(r0, r1, r2, r3, addr)                                          \
    asm volatile("ldmatrix.sync.aligned.m8n8.x4.shared.b16 {%0,%1,%2,%3}, [%4];" \
                 : "=r"(r0), "=r"(r1), "=r"(r2), "=r"(r3) : "r"(addr))

#define MMA16816(d, a, b0, b1)                                                 \
    asm volatile(                                                              \
        "mma.sync.aligned.m16n8k16.row.col.f32.f16.f16.f32 "                   \
        "{%0,%1,%2,%3},{%4,%5,%6,%7},{%8,%9},{%0,%1,%2,%3};"                   \
        : "+f"((d)[0]), "+f"((d)[1]), "+f"((d)[2]), "+f"((d)[3])               \
        : "r"((a)[0]), "r"((a)[1]), "r"((a)[2]), "r"((a)[3]),                  \
          "r"(b0), "r"(b1))

__device__ __forceinline__ uint32_t h2bits(float x, float y) {
    __half2 h = __floats2half2_rn(x, y);
    return *(uint32_t*)&h;
}

// ---------------- weight convert (fp32 -> fp16), all 4 weights in one -------
__global__ void cvt_all(const float* __restrict__ wq, const float* __restrict__ wp,
                        const float* __restrict__ w1, const float* __restrict__ w2) {
    int i = blockIdx.x * 256 + threadIdx.x;
    if (i < NWQ) g_Wq[i] = __float2half(wq[i]);
    if (i < NWP) g_Wp[i] = __float2half(wp[i]);
    if (i < NW1) g_W1[i] = __float2half(w1[i]);
    if (i < NW2) g_W2[i] = __float2half(w2[i]);
}

// ---------------- layernorm (warp per token), optional shift+window remap ----
template <bool SHIFT>
__global__ void __launch_bounds__(256) ln_kernel(const float* __restrict__ xin,
                                                 const float* __restrict__ gamma,
                                                 const float* __restrict__ beta) {
    int t    = (blockIdx.x * 256 + threadIdx.x) >> 5;
    int lane = threadIdx.x & 31;
    __half* ob = SHIFT ? g_XN1 : g_XN2;

    size_t src = SHIFT ? win_to_img(t) : (size_t)t;
    const float* row = xin + src * DIMC;

    float4 v[4];
    float sum = 0.f, sq = 0.f;
#pragma unroll
    for (int p = 0; p < 4; p++) {
        v[p] = *(const float4*)(row + p * 128 + lane * 4);
        sum += v[p].x + v[p].y + v[p].z + v[p].w;
        sq  += v[p].x * v[p].x + v[p].y * v[p].y + v[p].z * v[p].z + v[p].w * v[p].w;
    }
#pragma unroll
    for (int o = 16; o > 0; o >>= 1) {
        sum += __shfl_xor_sync(0xffffffffu, sum, o);
        sq  += __shfl_xor_sync(0xffffffffu, sq, o);
    }
    float mu   = sum * (1.f / 512.f);
    float var  = sq * (1.f / 512.f) - mu * mu;
    float rstd = rsqrtf(var + 1e-5f);

    __half* orow = ob + (size_t)t * DIMC;
#pragma unroll
    for (int p = 0; p < 4; p++) {
        int c = p * 128 + lane * 4;
        float4 g4 = *(const float4*)(gamma + c);
        float4 b4 = *(const float4*)(beta + c);
        __half2 h0 = __floats2half2_rn((v[p].x - mu) * rstd * g4.x + b4.x,
                                       (v[p].y - mu) * rstd * g4.y + b4.y);
        __half2 h1 = __floats2half2_rn((v[p].z - mu) * rstd * g4.z + b4.z,
                                       (v[p].w - mu) * rstd * g4.w + b4.w);
        uint2 u;
        u.x = *(uint32_t*)&h0;
        u.y = *(uint32_t*)&h1;
        *(uint2*)(orow + c) = u;
    }
}

// ---------------- fp16 mma.sync GEMM: C[M,N] = A[M,K] @ W[N,K]^T ------------
template <int NTOT, int KTOT, int OP>
__global__ void __launch_bounds__(256, 2) gemm_f16(const float* __restrict__ bias,
                                                   const float* __restrict__ aux,
                                                   float* __restrict__ outp) {
    constexpr int BM = 128, BN = 128, BK = 64, STAGES = 3;
    constexpr int KT = KTOT / BK;
    constexpr uint32_t AB    = BM * BK * 2;   // 16KB
    constexpr uint32_t BB    = BN * BK * 2;   // 16KB
    constexpr uint32_t STAGE = AB + BB;       // 32KB

    extern __shared__ char smem[];
    const uint32_t sbase = smem_u32(smem);
    const int tid = threadIdx.x;

    const __half* A;
    const __half* Bw;
    if (OP == 0)      { A = g_XN1; Bw = g_Wq; }
    else if (OP == 1) { A = g_O;   Bw = g_Wp; }
    else if (OP == 2) { A = g_XN2; Bw = g_W1; }
    else              { A = g_H1;  Bw = g_W2; }

    const int m0 = blockIdx.y * BM;
    const int n0 = blockIdx.x * BN;

    auto load_tile = [&](int kt, int s) {
        const __half* gA = A + (size_t)m0 * KTOT + kt * BK;
        const __half* gB = Bw + (size_t)n0 * KTOT + kt * BK;
#pragma unroll
        for (int i = 0; i < 4; i++) {
            int idx = i * 256 + tid;
            int r = idx >> 3, g = idx & 7;
            uint32_t off = (uint32_t)(r * 128 + ((g ^ (r & 7)) << 4));
            uint32_t da = sbase + (uint32_t)s * STAGE + off;
            const __half* pa = gA + (size_t)r * KTOT + g * 8;
            asm volatile("cp.async.cg.shared.global [%0], [%1], 16;\n" ::"r"(da), "l"(pa));
            uint32_t db = sbase + (uint32_t)s * STAGE + AB + off;
            const __half* pb = gB + (size_t)r * KTOT + g * 8;
            asm volatile("cp.async.cg.shared.global [%0], [%1], 16;\n" ::"r"(db), "l"(pb));
        }
        asm volatile("cp.async.commit_group;\n");
    };

    const int w    = tid >> 5;
    const int wm   = w >> 2;
    const int wn   = w & 3;
    const int lane = tid & 31;
    const int grp  = lane >> 2;
    const int tig  = lane & 3;

    float acc[4][4][4];
#pragma unroll
    for (int i = 0; i < 4; i++)
#pragma unroll
        for (int j = 0; j < 4; j++)
#pragma unroll
            for (int r = 0; r < 4; r++) acc[i][j][r] = 0.f;

    const int a_row  = wm * 64 + (lane & 15);
    const int a_chk0 = lane >> 4;
    const int b_row  = wn * 32 + (lane & 7) + ((lane >> 4) << 3);
    const int b_chk0 = (lane >> 3) & 1;

    load_tile(0, 0);
    load_tile(1, 1);

#pragma unroll 1
    for (int kt = 0; kt < KT; ++kt) {
        if (kt + 2 < KT) asm volatile("cp.async.wait_group 1;\n");
        else             asm volatile("cp.async.wait_group 0;\n");
        __syncthreads();

        if (kt + 2 < KT) load_tile(kt + 2, (kt + 2) % STAGES);

        const uint32_t stA = sbase + (uint32_t)(kt % STAGES) * STAGE;
        const uint32_t stB = stA + AB;

#pragma unroll
        for (int ks = 0; ks < 4; ++ks) {
            uint32_t a[4][4], b[2][4];
#pragma unroll
            for (int mt = 0; mt < 4; ++mt) {
                int r = a_row + mt * 16;
                int c = ks * 2 + a_chk0;
                uint32_t ad = stA + (uint32_t)(r * 128 + ((c ^ (r & 7)) << 4));
                LDSM_X4(a[mt][0], a[mt][1], a[mt][2], a[mt][3], ad);
            }
#pragma unroll
            for (int nt2 = 0; nt2 < 2; ++nt2) {
                int r = b_row + nt2 * 16;
                int c = ks * 2 + b_chk0;
                uint32_t bd = stB + (uint32_t)(r * 128 + ((c ^ (r & 7)) << 4));
                LDSM_X4(b[nt2][0], b[nt2][1], b[nt2][2], b[nt2][3], bd);
            }
#pragma unroll
            for (int mt = 0; mt < 4; ++mt)
#pragma unroll
                for (int nt = 0; nt < 4; ++nt)
                    MMA16816(acc[mt][nt], a[mt], b[nt >> 1][(nt & 1) * 2], b[nt >> 1][(nt & 1) * 2 + 1]);
        }
    }

    // ---- epilogue ----
#pragma unroll
    for (int mt = 0; mt < 4; ++mt) {
        int r_lo = m0 + wm * 64 + mt * 16 + grp;
        int r_hi = r_lo + 8;
        size_t d_lo = 0, d_hi = 0;
        if (OP == 1) {
            d_lo = win_to_img(r_lo) * DIMC;
            d_hi = win_to_img(r_hi) * DIMC;
        }
#pragma unroll
        for (int nt = 0; nt < 4; ++nt) {
            int c0 = n0 + wn * 32 + nt * 8 + 2 * tig;
            float b0 = bias[c0], b1 = bias[c0 + 1];
            float v00 = acc[mt][nt][0] + b0;
            float v01 = acc[mt][nt][1] + b1;
            float v10 = acc[mt][nt][2] + b0;
            float v11 = acc[mt][nt][3] + b1;
            if (OP == 0) {
                *(__half2*)(g_QKV + (size_t)r_lo * NTOT + c0) = __floats2half2_rn(v00, v01);
                *(__half2*)(g_QKV + (size_t)r_hi * NTOT + c0) = __floats2half2_rn(v10, v11);
            } else if (OP == 1) {
                float2 a0 = *(const float2*)(aux + d_lo + c0);
                float2 a1 = *(const float2*)(aux + d_hi + c0);
                *(float2*)(outp + d_lo + c0) = make_float2(a0.x + v00, a0.y + v01);
                *(float2*)(outp + d_hi + c0) = make_float2(a1.x + v10, a1.y + v11);
            } else if (OP == 2) {
                *(__half2*)(g_H1 + (size_t)r_lo * NTOT + c0) =
                    __floats2half2_rn(gelu_f(v00), gelu_f(v01));
                *(__half2*)(g_H1 + (size_t)r_hi * NTOT + c0) =
                    __floats2half2_rn(gelu_f(v10), gelu_f(v11));
            } else {
                size_t o0 = (size_t)r_lo * NTOT + c0;
                size_t o1 = (size_t)r_hi * NTOT + c0;
                float2 p0 = *(const float2*)(outp + o0);
                float2 p1 = *(const float2*)(outp + o1);
                *(float2*)(outp + o0) = make_float2(p0.x + v00, p0.y + v01);
                *(float2*)(outp + o1) = make_float2(p1.x + v10, p1.y + v11);
            }
        }
    }
}

// ---------------- attention via mma.sync: one 128-thread block per (win,head)
// Q,K in packed-swizzled smem (two 64B logical rows per 128B physical row),
// V transposed (32 x 64, 128B rows). S = Q@K^T on tensor cores; bias+mask+exp
// on fragments; P stays in registers as fp16 A-frags; O = P@V on tensor cores.
__global__ void __launch_bounds__(128) attn_kernel(const float* __restrict__ rpb) {
    __shared__ __align__(16) __half sQ[64 * 32];   // 4KB packed
    __shared__ __align__(16) __half sK[64 * 32];   // 4KB packed
    __shared__ __align__(16) __half sVt[32 * 64];  // 4KB (32 rows x 128B)
    __shared__ float srpb[225];
    __shared__ int   slab[64];

    const int bh   = blockIdx.x;
    const int b_   = bh >> 4;
    const int h    = bh & 15;
    const int tid  = threadIdx.x;
    const int w    = tid >> 5;
    const int lane = tid & 31;
    const int grp  = lane >> 2;
    const int tig  = lane & 3;

    const uint32_t qb = smem_u32(sQ);
    const uint32_t kb = smem_u32(sK);
    const uint32_t vb = smem_u32(sVt);

    // packed Q/K addressing: logical row r (0..63), chunk g (0..3 of 16B)
    auto qk_off = [](int r, int g) -> uint32_t {
        return (uint32_t)((r >> 1) * 128 + (((((r & 1) << 2) | g) ^ ((r >> 1) & 7)) << 4));
    };

    // ---- load Q, K (16B chunks), V transposed ----
    const __half* base = g_QKV + (size_t)(b_ * 64) * (3 * DIMC) + h * 32;
#pragma unroll
    for (int i = 0; i < 2; i++) {
        int idx = i * 128 + tid;          // 0..255
        int r = idx >> 2, g = idx & 3;
        const __half* rowp = base + (size_t)r * (3 * DIMC);
        *(uint4*)((char*)sQ + qk_off(r, g)) = *(const uint4*)(rowp + g * 8);
        *(uint4*)((char*)sK + qk_off(r, g)) = *(const uint4*)(rowp + DIMC + g * 8);
        // V transpose: token r, dims g*8..g*8+7 -> sVt[d][r]
        uint4 uv = *(const uint4*)(rowp + 2 * DIMC + g * 8);
        const __half* hv = (const __half*)&uv;
#pragma unroll
        for (int j = 0; j < 8; j++) {
            int d = g * 8 + j;
            uint32_t off = (uint32_t)(d * 128 + (((r >> 3) ^ (d & 7)) << 4) + (r & 7) * 2);
            *(__half*)((char*)sVt + off) = hv[j];
        }
    }
    if (tid < 64) {
        int widx = b_ & 63;
        int gh = ((widx >> 3) << 3) + (tid >> 3);
        int gw = ((widx & 7) << 3) + (tid & 7);
        int zh = gh < 56 ? 0 : (gh < 60 ? 1 : 2);
        int zw = gw < 56 ? 0 : (gw < 60 ? 1 : 2);
        slab[tid] = zh * 3 + zw;
    }
    for (int i = tid; i < 225; i += 128) srpb[i] = rpb[i * NHEADS + h];
    __syncthreads();

    // ---- S = Q @ K^T : warp w computes rows w*16..w*16+15, cols 0..63 ----
    float s[8][4];
#pragma unroll
    for (int i = 0; i < 8; i++)
#pragma unroll
        for (int j = 0; j < 4; j++) s[i][j] = 0.f;

    const int a_row  = w * 16 + (lane & 15);
    const int a_chk0 = lane >> 4;
    const int b_row  = (lane & 7) + ((lane >> 4) << 3);
    const int b_chk0 = (lane >> 3) & 1;

#pragma unroll
    for (int ks = 0; ks < 2; ++ks) {
        uint32_t a[4], b[4][4];
        LDSM_X4(a[0], a[1], a[2], a[3], qb + qk_off(a_row, ks * 2 + a_chk0));
#pragma unroll
        for (int nt2 = 0; nt2 < 4; ++nt2)
            LDSM_X4(b[nt2][0], b[nt2][1], b[nt2][2], b[nt2][3],
                    kb + qk_off(nt2 * 16 + b_row, ks * 2 + b_chk0));
#pragma unroll
        for (int nt = 0; nt < 8; ++nt)
            MMA16816(s[nt], a, b[nt >> 1][(nt & 1) * 2], b[nt >> 1][(nt & 1) * 2 + 1]);
    }

    // ---- bias + mask + exp on fragments; row sums ----
    const float scale = 0.17677669529663687f;  // 1/sqrt(32)
    const int r0 = w * 16 + grp;
    const int r1 = r0 + 8;
    const int rh0 = r0 >> 3, rw0 = r0 & 7;
    const int rh1 = r1 >> 3;
    const int lab0 = slab[r0], lab1 = slab[r1];

    float sum0 = 0.f, sum1 = 0.f;
#pragma unroll
    for (int nt = 0; nt < 8; ++nt) {
#pragma unroll
        for (int e = 0; e < 2; ++e) {
            int c  = nt * 8 + tig * 2 + e;
            int mh = c >> 3, mw = c & 7;
            int lb = slab[c];
            float bi0 = srpb[(rh0 - mh + 7) * 15 + (rw0 - mw + 7)];
            float bi1 = srpb[(rh1 - mh + 7) * 15 + (rw0 - mw + 7)];
            float v0 = s[nt][e]     * scale + bi0 + (lab0 == lb ? 0.f : -100.f);
            float v1 = s[nt][2 + e] * scale + bi1 + (lab1 == lb ? 0.f : -100.f);
            float e0 = __expf(v0);
            float e1 = __expf(v1);
            s[nt][e]     = e0;
            s[nt][2 + e] = e1;
            sum0 += e0;
            sum1 += e1;
        }
    }
    sum0 += __shfl_xor_sync(0xffffffffu, sum0, 1);
    sum0 += __shfl_xor_sync(0xffffffffu, sum0, 2);
    sum1 += __shfl_xor_sync(0xffffffffu, sum1, 1);
    sum1 += __shfl_xor_sync(0xffffffffu, sum1, 2);

    // ---- O = P @ V : P from registers (C-frag -> A-frag identity) ----
    float o[4][4];
#pragma unroll
    for (int i = 0; i < 4; i++)
#pragma unroll
        for (int j = 0; j < 4; j++) o[i][j] = 0.f;

#pragma unroll
    for (int ks2 = 0; ks2 < 4; ++ks2) {
        uint32_t pa[4];
        pa[0] = h2bits(s[ks2 * 2][0],     s[ks2 * 2][1]);
        pa[1] = h2bits(s[ks2 * 2][2],     s[ks2 * 2][3]);
        pa[2] = h2bits(s[ks2 * 2 + 1][0], s[ks2 * 2 + 1][1]);
        pa[3] = h2bits(s[ks2 * 2 + 1][2], s[ks2 * 2 + 1][3]);
        uint32_t b2[2][4];
#pragma unroll
        for (int nt2 = 0; nt2 < 2; ++nt2) {
            int r = nt2 * 16 + b_row;
            int c = ks2 * 2 + b_chk0;
            LDSM_X4(b2[nt2][0], b2[nt2][1], b2[nt2][2], b2[nt2][3],
                    vb + (uint32_t)(r * 128 + ((c ^ (r & 7)) << 4)));
        }
#pragma unroll
        for (int nt = 0; nt < 4; ++nt)
            MMA16816(o[nt], pa, b2[nt >> 1][(nt & 1) * 2], b2[nt >> 1][(nt & 1) * 2 + 1]);
    }

    const float inv0 = 1.f / sum0;
    const float inv1 = 1.f / sum1;
    __half* o0 = g_O + (size_t)(b_ * 64 + r0) * DIMC + h * 32;
    __half* o1 = g_O + (size_t)(b_ * 64 + r1) * DIMC + h * 32;
#pragma unroll
    for (int nt = 0; nt < 4; ++nt) {
        int d = nt * 8 + tig * 2;
        *(__half2*)(o0 + d) = __floats2half2_rn(o[nt][0] * inv0, o[nt][1] * inv0);
        *(__half2*)(o1 + d) = __floats2half2_rn(o[nt][2] * inv1, o[nt][3] * inv1);
    }
}

// ---------------- host launcher ----------------
extern "C" void kernel_launch(void* const* d_in, const int* in_sizes, int n_in,
                              void* d_out, int out_size) {
    const float* x      = (const float*)d_in[0];
    const float* n1g    = (const float*)d_in[1];
    const float* n1b    = (const float*)d_in[2];
    const float* qkv_w  = (const float*)d_in[3];
    const float* qkv_b  = (const float*)d_in[4];
    const float* proj_w = (const float*)d_in[5];
    const float* proj_b = (const float*)d_in[6];
    const float* rpb    = (const float*)d_in[7];
    const float* n2g    = (const float*)d_in[8];
    const float* n2b    = (const float*)d_in[9];
    const float* fc1_w  = (const float*)d_in[10];
    const float* fc1_b  = (const float*)d_in[11];
    const float* fc2_w  = (const float*)d_in[12];
    const float* fc2_b  = (const float*)d_in[13];
    float* out = (float*)d_out;

    constexpr int SMEMB = 3 * (128 * 64 * 2 + 128 * 64 * 2);  // 98304 bytes

    cudaFuncSetAttribute(gemm_f16<1536, 512, 0>, cudaFuncAttributeMaxDynamicSharedMemorySize, SMEMB);
    cudaFuncSetAttribute(gemm_f16<512,  512, 1>, cudaFuncAttributeMaxDynamicSharedMemorySize, SMEMB);
    cudaFuncSetAttribute(gemm_f16<2048, 512, 2>, cudaFuncAttributeMaxDynamicSharedMemorySize, SMEMB);
    cudaFuncSetAttribute(gemm_f16<512, 2048, 3>, cudaFuncAttributeMaxDynamicSharedMemorySize, SMEMB);

    // weights -> fp16 copies (single kernel)
    cvt_all<<<(NW1 + 255) / 256, 256>>>(qkv_w, proj_w, fc1_w, fc2_w);

    // LN1 + shift + window partition
    ln_kernel<true><<<MROWS / 8, 256>>>(x, n1g, n1b);

    // QKV projection
    gemm_f16<1536, 512, 0><<<dim3(1536 / 128, MROWS / 128), 256, SMEMB>>>(qkv_b, nullptr, nullptr);

    // windowed attention (tensor-core)
    attn_kernel<<<BWIN * NHEADS, 128>>>(rpb);

    // output projection + window reverse + shift + residual -> d_out
    gemm_f16<512, 512, 1><<<dim3(512 / 128, MROWS / 128), 256, SMEMB>>>(proj_b, x, out);

    // LN2
    ln_kernel<false><<<MROWS / 8, 256>>>(out, n2g, n2b);

    // FC1 + gelu
    gemm_f16<2048, 512, 2><<<dim3(2048 / 128, MROWS / 128), 256, SMEMB>>>(fc1_b, nullptr, nullptr);

    // FC2 + residual add into d_out
    gemm_f16<512, 2048, 3><<<dim3(512 / 128, MROWS / 128), 256, SMEMB>>>(fc2_b, nullptr, out);
}